// round 6
// baseline (speedup 1.0000x reference)
#include <cuda_runtime.h>

#define N_NODES 50000
#define N_EDGES 600000
#define DIM 128
#define N_LAYERS 3
#define N_GRAPHS 512
#define BN_EPS 1e-5f

#define ROWS_PER_BLK 64
#define H1_STRIDE 132   // padded row stride for H1 tile (floats)

// Scratch (device globals; no allocation allowed)
__device__ float g_agg[N_NODES * DIM];    // agg / h2 buffer (in-place reuse)
__device__ float g_h[N_NODES * DIM];      // h after BN
__device__ float g_stats[2 * DIM];        // per-feature sum, sumsq
__device__ float g_st[2 * DIM];           // per-feature scale, shift

// ---------------------------------------------------------------------------
// vector atomic add (sm_90+)
__device__ __forceinline__ void red_add_v4(float4* p, float4 v) {
    asm volatile("red.global.add.v4.f32 [%0], {%1, %2, %3, %4};\n"
                 :: "l"(p), "f"(v.x), "f"(v.y), "f"(v.z), "f"(v.w)
                 : "memory");
}

// ---------------------------------------------------------------------------
// K0 (layer 0 only): agg = x, zero BN stats accumulators
__global__ void k_init(const float4* __restrict__ x) {
    int idx = blockIdx.x * blockDim.x + threadIdx.x;  // 1.6M exact
    ((float4*)g_agg)[idx] = x[idx];
    if (blockIdx.x == 0 && threadIdx.x < 2 * DIM) g_stats[threadIdx.x] = 0.0f;
}

// ---------------------------------------------------------------------------
// K1: agg[dst] += h_in[src]  (warp per edge, lane per float4)
__global__ void k_scatter(const float4* __restrict__ x, int use_x,
                          const int* __restrict__ src, const int* __restrict__ dst) {
    int gt = blockIdx.x * blockDim.x + threadIdx.x;
    int e = gt >> 5;
    int lane = gt & 31;
    if (e >= N_EDGES) return;
    const float4* hin = use_x ? x : (const float4*)g_h;
    int s = __ldg(src + e);
    int d = __ldg(dst + e);
    float4 v = __ldg(hin + s * 32 + lane);
    red_add_v4((float4*)g_agg + d * 32 + lane, v);
}

// ---------------------------------------------------------------------------
// K2: fused MLP: h2 = relu(relu(agg@W1+b1)@W2+b2) in-place on g_agg,
//     plus BN statistic accumulation (sum, sumsq per feature).
__global__ __launch_bounds__(256, 1)
void k_mlp(const float4* __restrict__ W1, const float* __restrict__ b1,
           const float4* __restrict__ W2, const float* __restrict__ b2) {
    extern __shared__ float sm[];
    float*  As  = sm;                        // [64][128]
    float*  Ws  = sm + ROWS_PER_BLK * DIM;   // [128][128]
    float*  H1  = Ws + DIM * DIM;            // [64][132]
    float4* As4 = (float4*)As;
    float4* Ws4 = (float4*)Ws;

    const int tid  = threadIdx.x;
    const int base = blockIdx.x * ROWS_PER_BLK;

    // load W1 (4096 float4)
    #pragma unroll
    for (int i = 0; i < 16; i++) Ws4[tid + i * 256] = W1[tid + i * 256];
    // load A tile (2048 float4), zero-fill out-of-range rows
    const float4* A4 = (const float4*)g_agg;
    #pragma unroll
    for (int i = 0; i < 8; i++) {
        int idx = tid + i * 256;
        int r = idx >> 5, kq = idx & 31;
        float4 v = make_float4(0.f, 0.f, 0.f, 0.f);
        if (base + r < N_NODES) v = A4[(base + r) * 32 + kq];
        As4[idx] = v;
    }
    __syncthreads();

    const int colg = tid & 15;
    const int rowg = tid >> 4;
    const int c0 = colg * 8, r0 = rowg * 4;

    // ---- GEMM 1: acc = A @ W1 ----
    float acc[4][8];
    #pragma unroll
    for (int i = 0; i < 4; i++)
        #pragma unroll
        for (int j = 0; j < 8; j++) acc[i][j] = 0.f;

    #pragma unroll 4
    for (int k = 0; k < DIM; k++) {
        float a0 = As[(r0 + 0) * DIM + k];
        float a1 = As[(r0 + 1) * DIM + k];
        float a2 = As[(r0 + 2) * DIM + k];
        float a3 = As[(r0 + 3) * DIM + k];
        float4 w0 = Ws4[k * 32 + colg * 2];
        float4 w1 = Ws4[k * 32 + colg * 2 + 1];
        float w[8] = {w0.x, w0.y, w0.z, w0.w, w1.x, w1.y, w1.z, w1.w};
        #pragma unroll
        for (int j = 0; j < 8; j++) {
            acc[0][j] = fmaf(a0, w[j], acc[0][j]);
            acc[1][j] = fmaf(a1, w[j], acc[1][j]);
            acc[2][j] = fmaf(a2, w[j], acc[2][j]);
            acc[3][j] = fmaf(a3, w[j], acc[3][j]);
        }
    }

    // epilogue 1: relu(+b1) -> H1 smem
    #pragma unroll
    for (int j = 0; j < 8; j++) {
        float bb = __ldg(b1 + c0 + j);
        #pragma unroll
        for (int i = 0; i < 4; i++)
            H1[(r0 + i) * H1_STRIDE + c0 + j] = fmaxf(acc[i][j] + bb, 0.f);
    }
    __syncthreads();

    // load W2 over Ws; zero smem stat buffers (reusing As region, now idle)
    #pragma unroll
    for (int i = 0; i < 16; i++) Ws4[tid + i * 256] = W2[tid + i * 256];
    if (tid < DIM) { As[tid] = 0.f; As[DIM + tid] = 0.f; }
    __syncthreads();

    // ---- GEMM 2: acc = H1 @ W2 ----
    #pragma unroll
    for (int i = 0; i < 4; i++)
        #pragma unroll
        for (int j = 0; j < 8; j++) acc[i][j] = 0.f;

    #pragma unroll 4
    for (int k = 0; k < DIM; k++) {
        float a0 = H1[(r0 + 0) * H1_STRIDE + k];
        float a1 = H1[(r0 + 1) * H1_STRIDE + k];
        float a2 = H1[(r0 + 2) * H1_STRIDE + k];
        float a3 = H1[(r0 + 3) * H1_STRIDE + k];
        float4 w0 = Ws4[k * 32 + colg * 2];
        float4 w1 = Ws4[k * 32 + colg * 2 + 1];
        float w[8] = {w0.x, w0.y, w0.z, w0.w, w1.x, w1.y, w1.z, w1.w};
        #pragma unroll
        for (int j = 0; j < 8; j++) {
            acc[0][j] = fmaf(a0, w[j], acc[0][j]);
            acc[1][j] = fmaf(a1, w[j], acc[1][j]);
            acc[2][j] = fmaf(a2, w[j], acc[2][j]);
            acc[3][j] = fmaf(a3, w[j], acc[3][j]);
        }
    }

    // epilogue 2: relu(+b2), store h2, accumulate BN stats
    float v[4][8];
    #pragma unroll
    for (int j = 0; j < 8; j++) {
        float bb = __ldg(b2 + c0 + j);
        #pragma unroll
        for (int i = 0; i < 4; i++) v[i][j] = fmaxf(acc[i][j] + bb, 0.f);
    }

    float4* O4 = (float4*)g_agg;
    #pragma unroll
    for (int i = 0; i < 4; i++) {
        int row = base + r0 + i;
        if (row < N_NODES) {
            O4[row * 32 + colg * 2]     = make_float4(v[i][0], v[i][1], v[i][2], v[i][3]);
            O4[row * 32 + colg * 2 + 1] = make_float4(v[i][4], v[i][5], v[i][6], v[i][7]);
        }
    }

    // per-column partial sums over this thread's 4 rows (valid only)
    #pragma unroll
    for (int j = 0; j < 8; j++) {
        float s = 0.f, q = 0.f;
        #pragma unroll
        for (int i = 0; i < 4; i++) {
            if (base + r0 + i < N_NODES) { s += v[i][j]; q += v[i][j] * v[i][j]; }
        }
        atomicAdd(&As[c0 + j], s);
        atomicAdd(&As[DIM + c0 + j], q);
    }
    __syncthreads();
    if (tid < DIM) {
        atomicAdd(&g_stats[tid], As[tid]);
        atomicAdd(&g_stats[DIM + tid], As[DIM + tid]);
    }
}

// ---------------------------------------------------------------------------
// K3: finalize BN stats -> per-feature scale/shift
__global__ void k_finalize(const float* __restrict__ gamma, const float* __restrict__ beta) {
    int f = threadIdx.x;  // 128 threads
    float n = (float)N_NODES;
    float mean = g_stats[f] / n;
    float var = g_stats[DIM + f] / n - mean * mean;
    var = fmaxf(var, 0.f);
    float sc = rsqrtf(var + BN_EPS) * __ldg(gamma + f);
    g_st[f] = sc;
    g_st[DIM + f] = fmaf(-mean, sc, __ldg(beta + f));
}

// ---------------------------------------------------------------------------
// K4: apply BN -> g_h AND g_agg (pre-init next layer's aggregation buffer),
//     pool into output, and zero g_stats for the next layer.
__global__ void k_apply(const int* __restrict__ batch, float* __restrict__ out, int layer) {
    int idx = blockIdx.x * blockDim.x + threadIdx.x;  // 1.6M exact
    int row = idx >> 5, cq = idx & 31;
    float4 xv = ((const float4*)g_agg)[idx];
    float4 s = ((const float4*)g_st)[cq];
    float4 t = ((const float4*)g_st)[32 + cq];
    float4 y;
    y.x = fmaf(xv.x, s.x, t.x);
    y.y = fmaf(xv.y, s.y, t.y);
    y.z = fmaf(xv.z, s.z, t.z);
    y.w = fmaf(xv.w, s.w, t.w);
    ((float4*)g_h)[idx] = y;
    ((float4*)g_agg)[idx] = y;   // next layer: agg starts as h (self term)
    int g = __ldg(batch + row);
    red_add_v4((float4*)(out + g * (N_LAYERS * DIM) + layer * DIM + (cq << 2)), y);
    if (blockIdx.x == 0 && threadIdx.x < 2 * DIM) g_stats[threadIdx.x] = 0.0f;
}

// ---------------------------------------------------------------------------
extern "C" void kernel_launch(void* const* d_in, const int* in_sizes, int n_in,
                              void* d_out, int out_size) {
    const float* x      = (const float*)d_in[0];
    const int*   ei     = (const int*)d_in[1];
    const int*   batch  = (const int*)d_in[2];
    const float* W1s    = (const float*)d_in[3];
    const float* b1s    = (const float*)d_in[4];
    const float* W2s    = (const float*)d_in[5];
    const float* b2s    = (const float*)d_in[6];
    const float* gammas = (const float*)d_in[7];
    const float* betas  = (const float*)d_in[8];
    float* out = (float*)d_out;

    const int smem_mlp = (ROWS_PER_BLK * DIM + DIM * DIM + ROWS_PER_BLK * H1_STRIDE) * 4;
    cudaFuncSetAttribute(k_mlp, cudaFuncAttributeMaxDynamicSharedMemorySize, smem_mlp);

    cudaMemsetAsync(out, 0, (size_t)N_GRAPHS * N_LAYERS * DIM * sizeof(float));

    const int* src = ei;
    const int* dst = ei + N_EDGES;

    const int node_blocks    = (N_NODES * 32) / 256;              // 6250
    const int scatter_blocks = (N_EDGES * 32) / 256;              // 75000
    const int mlp_blocks     = (N_NODES + ROWS_PER_BLK - 1) / ROWS_PER_BLK;  // 782

    k_init<<<node_blocks, 256>>>((const float4*)x);
    for (int l = 0; l < N_LAYERS; l++) {
        int use_x = (l == 0) ? 1 : 0;
        k_scatter<<<scatter_blocks, 256>>>((const float4*)x, use_x, src, dst);
        k_mlp<<<mlp_blocks, 256, smem_mlp>>>(
            (const float4*)(W1s + l * DIM * DIM), b1s + l * DIM,
            (const float4*)(W2s + l * DIM * DIM), b2s + l * DIM);
        k_finalize<<<1, DIM>>>(gammas + l * DIM, betas + l * DIM);
        k_apply<<<node_blocks, 256>>>(batch, out, l);
    }
}

// round 7
// speedup vs baseline: 1.0061x; 1.0061x over previous
#include <cuda_runtime.h>

#define N_NODES 50000
#define N_EDGES 600000
#define DIM 128
#define N_LAYERS 3
#define N_GRAPHS 512
#define BN_EPS 1e-5f

#define ROWS_PER_BLK 64
#define H1_STRIDE 132   // padded row stride for H1 tile (floats)

// Scratch (device globals; no allocation allowed)
__device__ float g_agg[N_NODES * DIM];    // agg / h2 buffer (in-place reuse)
__device__ float g_h[N_NODES * DIM];      // h after BN
__device__ float g_stats[2 * DIM];        // per-feature sum, sumsq

// ---------------------------------------------------------------------------
// vector atomic add (sm_90+)
__device__ __forceinline__ void red_add_v4(float4* p, float4 v) {
    asm volatile("red.global.add.v4.f32 [%0], {%1, %2, %3, %4};\n"
                 :: "l"(p), "f"(v.x), "f"(v.y), "f"(v.z), "f"(v.w)
                 : "memory");
}

// packed f32x2 FMA (sm_100+; ptxas never auto-emits — PTX only)
__device__ __forceinline__ void fma2(unsigned long long& d,
                                     unsigned long long a, unsigned long long b) {
    asm("fma.rn.f32x2 %0, %1, %2, %0;" : "+l"(d) : "l"(a), "l"(b));
}
__device__ __forceinline__ unsigned long long pack2(float x) {
    unsigned long long r;
    asm("mov.b64 %0, {%1, %1};" : "=l"(r) : "f"(x));
    return r;
}
__device__ __forceinline__ float2 unpack2(unsigned long long v) {
    float2 f;
    asm("mov.b64 {%0, %1}, %2;" : "=f"(f.x), "=f"(f.y) : "l"(v));
    return f;
}

// ---------------------------------------------------------------------------
// K0 (layer 0 only): agg = x, zero BN stats accumulators
__global__ void k_init(const float4* __restrict__ x) {
    int idx = blockIdx.x * blockDim.x + threadIdx.x;  // 1.6M exact
    ((float4*)g_agg)[idx] = x[idx];
    if (blockIdx.x == 0 && threadIdx.x < 2 * DIM) g_stats[threadIdx.x] = 0.0f;
}

// ---------------------------------------------------------------------------
// K1: agg[dst] += h_in[src]  (warp per edge, lane per float4)
//     Block 0 also zeroes g_stats for the upcoming k_mlp accumulation.
__global__ void k_scatter(const float4* __restrict__ x, int use_x,
                          const int* __restrict__ src, const int* __restrict__ dst) {
    if (blockIdx.x == 0 && threadIdx.x < 2 * DIM) g_stats[threadIdx.x] = 0.0f;
    int gt = blockIdx.x * blockDim.x + threadIdx.x;
    int e = gt >> 5;
    int lane = gt & 31;
    if (e >= N_EDGES) return;
    const float4* hin = use_x ? x : (const float4*)g_h;
    int s = __ldg(src + e);
    int d = __ldg(dst + e);
    float4 v = __ldg(hin + s * 32 + lane);
    red_add_v4((float4*)g_agg + d * 32 + lane, v);
}

// ---------------------------------------------------------------------------
// K2: fused MLP: h2 = relu(relu(agg@W1+b1)@W2+b2) in-place on g_agg,
//     plus BN statistic accumulation (sum, sumsq per feature).
//     GEMM math via packed fma.rn.f32x2 (2 fp32 MACs / instruction).
__global__ __launch_bounds__(256, 1)
void k_mlp(const float4* __restrict__ W1, const float* __restrict__ b1,
           const float4* __restrict__ W2, const float* __restrict__ b2) {
    extern __shared__ float sm[];
    float*  As  = sm;                        // [64][128]
    float*  Ws  = sm + ROWS_PER_BLK * DIM;   // [128][128]
    float*  H1  = Ws + DIM * DIM;            // [64][132]
    float4* As4 = (float4*)As;
    float4* Ws4 = (float4*)Ws;
    const ulonglong2* Wp = (const ulonglong2*)Ws;

    const int tid  = threadIdx.x;
    const int base = blockIdx.x * ROWS_PER_BLK;

    // load W1 (4096 float4)
    #pragma unroll
    for (int i = 0; i < 16; i++) Ws4[tid + i * 256] = W1[tid + i * 256];
    // load A tile (2048 float4), zero-fill out-of-range rows
    const float4* A4 = (const float4*)g_agg;
    #pragma unroll
    for (int i = 0; i < 8; i++) {
        int idx = tid + i * 256;
        int r = idx >> 5, kq = idx & 31;
        float4 v = make_float4(0.f, 0.f, 0.f, 0.f);
        if (base + r < N_NODES) v = A4[(base + r) * 32 + kq];
        As4[idx] = v;
    }
    __syncthreads();

    const int colg = tid & 15;
    const int rowg = tid >> 4;
    const int c0 = colg * 8, r0 = rowg * 4;

    // ---- GEMM 1: acc = A @ W1  (f32x2: 4 rows x 4 col-pairs) ----
    unsigned long long acc[4][4];
    #pragma unroll
    for (int i = 0; i < 4; i++)
        #pragma unroll
        for (int p = 0; p < 4; p++) acc[i][p] = 0ull;

    #pragma unroll 4
    for (int k = 0; k < DIM; k++) {
        unsigned long long a0 = pack2(As[(r0 + 0) * DIM + k]);
        unsigned long long a1 = pack2(As[(r0 + 1) * DIM + k]);
        unsigned long long a2 = pack2(As[(r0 + 2) * DIM + k]);
        unsigned long long a3 = pack2(As[(r0 + 3) * DIM + k]);
        ulonglong2 q0 = Wp[k * 32 + colg * 2];
        ulonglong2 q1 = Wp[k * 32 + colg * 2 + 1];
        fma2(acc[0][0], a0, q0.x); fma2(acc[0][1], a0, q0.y);
        fma2(acc[0][2], a0, q1.x); fma2(acc[0][3], a0, q1.y);
        fma2(acc[1][0], a1, q0.x); fma2(acc[1][1], a1, q0.y);
        fma2(acc[1][2], a1, q1.x); fma2(acc[1][3], a1, q1.y);
        fma2(acc[2][0], a2, q0.x); fma2(acc[2][1], a2, q0.y);
        fma2(acc[2][2], a2, q1.x); fma2(acc[2][3], a2, q1.y);
        fma2(acc[3][0], a3, q0.x); fma2(acc[3][1], a3, q0.y);
        fma2(acc[3][2], a3, q1.x); fma2(acc[3][3], a3, q1.y);
    }

    // epilogue 1: relu(+b1) -> H1 smem
    #pragma unroll
    for (int p = 0; p < 4; p++) {
        float b_lo = __ldg(b1 + c0 + 2 * p);
        float b_hi = __ldg(b1 + c0 + 2 * p + 1);
        #pragma unroll
        for (int i = 0; i < 4; i++) {
            float2 f = unpack2(acc[i][p]);
            H1[(r0 + i) * H1_STRIDE + c0 + 2 * p]     = fmaxf(f.x + b_lo, 0.f);
            H1[(r0 + i) * H1_STRIDE + c0 + 2 * p + 1] = fmaxf(f.y + b_hi, 0.f);
        }
    }
    __syncthreads();

    // load W2 over Ws; zero smem stat buffers (reusing As region, now idle)
    #pragma unroll
    for (int i = 0; i < 16; i++) Ws4[tid + i * 256] = W2[tid + i * 256];
    if (tid < DIM) { As[tid] = 0.f; As[DIM + tid] = 0.f; }
    __syncthreads();

    // ---- GEMM 2: acc = H1 @ W2 ----
    #pragma unroll
    for (int i = 0; i < 4; i++)
        #pragma unroll
        for (int p = 0; p < 4; p++) acc[i][p] = 0ull;

    #pragma unroll 4
    for (int k = 0; k < DIM; k++) {
        unsigned long long a0 = pack2(H1[(r0 + 0) * H1_STRIDE + k]);
        unsigned long long a1 = pack2(H1[(r0 + 1) * H1_STRIDE + k]);
        unsigned long long a2 = pack2(H1[(r0 + 2) * H1_STRIDE + k]);
        unsigned long long a3 = pack2(H1[(r0 + 3) * H1_STRIDE + k]);
        ulonglong2 q0 = Wp[k * 32 + colg * 2];
        ulonglong2 q1 = Wp[k * 32 + colg * 2 + 1];
        fma2(acc[0][0], a0, q0.x); fma2(acc[0][1], a0, q0.y);
        fma2(acc[0][2], a0, q1.x); fma2(acc[0][3], a0, q1.y);
        fma2(acc[1][0], a1, q0.x); fma2(acc[1][1], a1, q0.y);
        fma2(acc[1][2], a1, q1.x); fma2(acc[1][3], a1, q1.y);
        fma2(acc[2][0], a2, q0.x); fma2(acc[2][1], a2, q0.y);
        fma2(acc[2][2], a2, q1.x); fma2(acc[2][3], a2, q1.y);
        fma2(acc[3][0], a3, q0.x); fma2(acc[3][1], a3, q0.y);
        fma2(acc[3][2], a3, q1.x); fma2(acc[3][3], a3, q1.y);
    }

    // epilogue 2: relu(+b2), store h2, accumulate BN stats
    float v[4][8];
    #pragma unroll
    for (int p = 0; p < 4; p++) {
        float b_lo = __ldg(b2 + c0 + 2 * p);
        float b_hi = __ldg(b2 + c0 + 2 * p + 1);
        #pragma unroll
        for (int i = 0; i < 4; i++) {
            float2 f = unpack2(acc[i][p]);
            v[i][2 * p]     = fmaxf(f.x + b_lo, 0.f);
            v[i][2 * p + 1] = fmaxf(f.y + b_hi, 0.f);
        }
    }

    float4* O4 = (float4*)g_agg;
    #pragma unroll
    for (int i = 0; i < 4; i++) {
        int row = base + r0 + i;
        if (row < N_NODES) {
            O4[row * 32 + colg * 2]     = make_float4(v[i][0], v[i][1], v[i][2], v[i][3]);
            O4[row * 32 + colg * 2 + 1] = make_float4(v[i][4], v[i][5], v[i][6], v[i][7]);
        }
    }

    // per-column partial sums over this thread's 4 rows (valid only)
    #pragma unroll
    for (int j = 0; j < 8; j++) {
        float s = 0.f, q = 0.f;
        #pragma unroll
        for (int i = 0; i < 4; i++) {
            if (base + r0 + i < N_NODES) { s += v[i][j]; q += v[i][j] * v[i][j]; }
        }
        atomicAdd(&As[c0 + j], s);
        atomicAdd(&As[DIM + c0 + j], q);
    }
    __syncthreads();
    if (tid < DIM) {
        atomicAdd(&g_stats[tid], As[tid]);
        atomicAdd(&g_stats[DIM + tid], As[DIM + tid]);
    }
}

// ---------------------------------------------------------------------------
// K3: apply BN -> g_h AND g_agg (pre-init next layer's aggregation buffer),
//     pool into output. Scale/shift computed per-block from g_stats
//     (redundant but trivially cheap; removes the k_finalize launch).
__global__ void k_apply(const int* __restrict__ batch, float* __restrict__ out,
                        const float* __restrict__ gamma, const float* __restrict__ beta,
                        int layer) {
    __shared__ float s_st[2 * DIM];
    if (threadIdx.x < DIM) {
        int f = threadIdx.x;
        float n = (float)N_NODES;
        float mean = g_stats[f] / n;
        float var = g_stats[DIM + f] / n - mean * mean;
        var = fmaxf(var, 0.f);
        float sc = rsqrtf(var + BN_EPS) * __ldg(gamma + f);
        s_st[f] = sc;
        s_st[DIM + f] = fmaf(-mean, sc, __ldg(beta + f));
    }
    __syncthreads();

    int idx = blockIdx.x * blockDim.x + threadIdx.x;  // 1.6M exact
    int row = idx >> 5, cq = idx & 31;
    float4 xv = ((const float4*)g_agg)[idx];
    float4 s = ((const float4*)s_st)[cq];
    float4 t = ((const float4*)s_st)[32 + cq];
    float4 y;
    y.x = fmaf(xv.x, s.x, t.x);
    y.y = fmaf(xv.y, s.y, t.y);
    y.z = fmaf(xv.z, s.z, t.z);
    y.w = fmaf(xv.w, s.w, t.w);
    ((float4*)g_h)[idx] = y;
    ((float4*)g_agg)[idx] = y;   // next layer: agg starts as h (self term)
    int g = __ldg(batch + row);
    red_add_v4((float4*)(out + g * (N_LAYERS * DIM) + layer * DIM + (cq << 2)), y);
}

// ---------------------------------------------------------------------------
extern "C" void kernel_launch(void* const* d_in, const int* in_sizes, int n_in,
                              void* d_out, int out_size) {
    const float* x      = (const float*)d_in[0];
    const int*   ei     = (const int*)d_in[1];
    const int*   batch  = (const int*)d_in[2];
    const float* W1s    = (const float*)d_in[3];
    const float* b1s    = (const float*)d_in[4];
    const float* W2s    = (const float*)d_in[5];
    const float* b2s    = (const float*)d_in[6];
    const float* gammas = (const float*)d_in[7];
    const float* betas  = (const float*)d_in[8];
    float* out = (float*)d_out;

    const int smem_mlp = (ROWS_PER_BLK * DIM + DIM * DIM + ROWS_PER_BLK * H1_STRIDE) * 4;
    cudaFuncSetAttribute(k_mlp, cudaFuncAttributeMaxDynamicSharedMemorySize, smem_mlp);

    cudaMemsetAsync(out, 0, (size_t)N_GRAPHS * N_LAYERS * DIM * sizeof(float));

    const int* src = ei;
    const int* dst = ei + N_EDGES;

    const int node_blocks    = (N_NODES * 32) / 256;              // 6250
    const int scatter_blocks = (N_EDGES * 32) / 256;              // 75000
    const int mlp_blocks     = (N_NODES + ROWS_PER_BLK - 1) / ROWS_PER_BLK;  // 782

    k_init<<<node_blocks, 256>>>((const float4*)x);
    for (int l = 0; l < N_LAYERS; l++) {
        int use_x = (l == 0) ? 1 : 0;
        k_scatter<<<scatter_blocks, 256>>>((const float4*)x, use_x, src, dst);
        k_mlp<<<mlp_blocks, 256, smem_mlp>>>(
            (const float4*)(W1s + l * DIM * DIM), b1s + l * DIM,
            (const float4*)(W2s + l * DIM * DIM), b2s + l * DIM);
        k_apply<<<node_blocks, 256>>>(batch, out, gammas + l * DIM, betas + l * DIM, l);
    }
}

// round 9
// speedup vs baseline: 1.2065x; 1.1992x over previous
#include <cuda_runtime.h>

#define N_NODES 50000
#define N_EDGES 600000
#define DIM 128
#define N_LAYERS 3
#define N_GRAPHS 512
#define BN_EPS 1e-5f

#define ROWS_PER_BLK 64
#define H1_STRIDE 132   // padded row stride for H1 tile (floats)

#define SCAN_BLOCKS 196          // ceil(50000/256)
#define SCAN_PAD (SCAN_BLOCKS*256)

// Scratch (device globals; no allocation allowed)
__device__ float g_agg[N_NODES * DIM];    // agg / h2 buffer (in-place reuse)
__device__ float g_h[N_NODES * DIM];      // h after BN
__device__ float g_stats[2 * DIM];        // per-feature sum, sumsq
// CSR build scratch
__device__ int g_deg[N_NODES];
__device__ int g_cur[N_NODES];
__device__ int g_off[N_NODES];
__device__ int g_scan[SCAN_PAD];
__device__ int g_bsum[256];
__device__ int g_esrc[N_EDGES];

// ---------------------------------------------------------------------------
// vector atomic add (sm_90+)
__device__ __forceinline__ void red_add_v4(float4* p, float4 v) {
    asm volatile("red.global.add.v4.f32 [%0], {%1, %2, %3, %4};\n"
                 :: "l"(p), "f"(v.x), "f"(v.y), "f"(v.z), "f"(v.w)
                 : "memory");
}

// packed f32x2 FMA (sm_100+; ptxas never auto-emits — PTX only)
__device__ __forceinline__ void fma2(unsigned long long& d,
                                     unsigned long long a, unsigned long long b) {
    asm("fma.rn.f32x2 %0, %1, %2, %0;" : "+l"(d) : "l"(a), "l"(b));
}
__device__ __forceinline__ unsigned long long pack2(float x) {
    unsigned long long r;
    asm("mov.b64 %0, {%1, %1};" : "=l"(r) : "f"(x));
    return r;
}
__device__ __forceinline__ float2 unpack2(unsigned long long v) {
    float2 f;
    asm("mov.b64 {%0, %1}, %2;" : "=f"(f.x), "=f"(f.y) : "l"(v));
    return f;
}

// ===========================================================================
// CSR build (once per call; edge list is identical for all 3 layers)
// ===========================================================================
__global__ void k_zero_counts() {
    int i = blockIdx.x * blockDim.x + threadIdx.x;
    if (i < N_NODES) { g_deg[i] = 0; g_cur[i] = 0; }
}

__global__ void k_hist(const int* __restrict__ dst) {
    int e = blockIdx.x * blockDim.x + threadIdx.x;
    if (e < N_EDGES) atomicAdd(&g_deg[__ldg(dst + e)], 1);
}

// block-wise inclusive scan of g_deg (padded with zeros)
__global__ void k_scan1() {
    __shared__ int s[256];
    int i = blockIdx.x * 256 + threadIdx.x;
    int v = (i < N_NODES) ? g_deg[i] : 0;
    s[threadIdx.x] = v;
    __syncthreads();
    #pragma unroll
    for (int d = 1; d < 256; d <<= 1) {
        int x = (threadIdx.x >= d) ? s[threadIdx.x - d] : 0;
        __syncthreads();
        s[threadIdx.x] += x;
        __syncthreads();
    }
    g_scan[i] = s[threadIdx.x];
    if (threadIdx.x == 255) g_bsum[blockIdx.x] = s[255];
}

// inclusive scan of the block sums (single block)
__global__ void k_scan2() {
    __shared__ int s[256];
    int v = (threadIdx.x < SCAN_BLOCKS) ? g_bsum[threadIdx.x] : 0;
    s[threadIdx.x] = v;
    __syncthreads();
    #pragma unroll
    for (int d = 1; d < 256; d <<= 1) {
        int x = (threadIdx.x >= d) ? s[threadIdx.x - d] : 0;
        __syncthreads();
        s[threadIdx.x] += x;
        __syncthreads();
    }
    g_bsum[threadIdx.x] = s[threadIdx.x];
}

// exclusive offsets: off[i] = incl_scan[i] - deg[i] + carry(block)
__global__ void k_scan3() {
    int i = blockIdx.x * 256 + threadIdx.x;
    if (i >= N_NODES) return;
    int carry = (blockIdx.x > 0) ? g_bsum[blockIdx.x - 1] : 0;
    g_off[i] = g_scan[i] - g_deg[i] + carry;
}

__global__ void k_place(const int* __restrict__ src, const int* __restrict__ dst) {
    int e = blockIdx.x * blockDim.x + threadIdx.x;
    if (e >= N_EDGES) return;
    int d = __ldg(dst + e);
    int pos = g_off[d] + atomicAdd(&g_cur[d], 1);
    g_esrc[pos] = __ldg(src + e);
}

// ===========================================================================
// K1: gather-aggregate: agg[n] = h_in[n] + sum_{e in CSR(n)} h_in[src[e]]
//     warp per node, lane per float4. No atomics. Also zeroes g_stats.
// ===========================================================================
__global__ void k_agg(const float4* __restrict__ x, int use_x) {
    if (blockIdx.x == 0 && threadIdx.x < 2 * DIM) g_stats[threadIdx.x] = 0.0f;
    int gt = blockIdx.x * blockDim.x + threadIdx.x;
    int node = gt >> 5;
    int lane = gt & 31;
    if (node >= N_NODES) return;
    const float4* hin = use_x ? x : (const float4*)g_h;

    float4 acc = __ldg(hin + node * 32 + lane);   // self term (eps=0)
    int e   = __ldg(g_off + node);
    int end = e + __ldg(g_deg + node);

    for (; e + 1 < end; e += 2) {                 // MLP=2
        int s0 = __ldg(g_esrc + e);
        int s1 = __ldg(g_esrc + e + 1);
        float4 v0 = __ldg(hin + s0 * 32 + lane);
        float4 v1 = __ldg(hin + s1 * 32 + lane);
        acc.x += v0.x; acc.y += v0.y; acc.z += v0.z; acc.w += v0.w;
        acc.x += v1.x; acc.y += v1.y; acc.z += v1.z; acc.w += v1.w;
    }
    if (e < end) {
        int s0 = __ldg(g_esrc + e);
        float4 v0 = __ldg(hin + s0 * 32 + lane);
        acc.x += v0.x; acc.y += v0.y; acc.z += v0.z; acc.w += v0.w;
    }
    ((float4*)g_agg)[node * 32 + lane] = acc;
}

// ===========================================================================
// K2: fused MLP: h2 = relu(relu(agg@W1+b1)@W2+b2) in-place on g_agg,
//     plus BN statistic accumulation (sum, sumsq per feature).
// ===========================================================================
__global__ __launch_bounds__(256, 1)
void k_mlp(const float4* __restrict__ W1, const float* __restrict__ b1,
           const float4* __restrict__ W2, const float* __restrict__ b2) {
    extern __shared__ float sm[];
    float*  As  = sm;                        // [64][128]
    float*  Ws  = sm + ROWS_PER_BLK * DIM;   // [128][128]
    float*  H1  = Ws + DIM * DIM;            // [64][132]
    float4* As4 = (float4*)As;
    float4* Ws4 = (float4*)Ws;
    const ulonglong2* Wp = (const ulonglong2*)Ws;

    const int tid  = threadIdx.x;
    const int base = blockIdx.x * ROWS_PER_BLK;

    #pragma unroll
    for (int i = 0; i < 16; i++) Ws4[tid + i * 256] = W1[tid + i * 256];
    const float4* A4 = (const float4*)g_agg;
    #pragma unroll
    for (int i = 0; i < 8; i++) {
        int idx = tid + i * 256;
        int r = idx >> 5, kq = idx & 31;
        float4 v = make_float4(0.f, 0.f, 0.f, 0.f);
        if (base + r < N_NODES) v = A4[(base + r) * 32 + kq];
        As4[idx] = v;
    }
    __syncthreads();

    const int colg = tid & 15;
    const int rowg = tid >> 4;
    const int c0 = colg * 8, r0 = rowg * 4;

    // ---- GEMM 1: acc = A @ W1  (f32x2) ----
    unsigned long long acc[4][4];
    #pragma unroll
    for (int i = 0; i < 4; i++)
        #pragma unroll
        for (int p = 0; p < 4; p++) acc[i][p] = 0ull;

    #pragma unroll 4
    for (int k = 0; k < DIM; k++) {
        unsigned long long a0 = pack2(As[(r0 + 0) * DIM + k]);
        unsigned long long a1 = pack2(As[(r0 + 1) * DIM + k]);
        unsigned long long a2 = pack2(As[(r0 + 2) * DIM + k]);
        unsigned long long a3 = pack2(As[(r0 + 3) * DIM + k]);
        ulonglong2 q0 = Wp[k * 32 + colg * 2];
        ulonglong2 q1 = Wp[k * 32 + colg * 2 + 1];
        fma2(acc[0][0], a0, q0.x); fma2(acc[0][1], a0, q0.y);
        fma2(acc[0][2], a0, q1.x); fma2(acc[0][3], a0, q1.y);
        fma2(acc[1][0], a1, q0.x); fma2(acc[1][1], a1, q0.y);
        fma2(acc[1][2], a1, q1.x); fma2(acc[1][3], a1, q1.y);
        fma2(acc[2][0], a2, q0.x); fma2(acc[2][1], a2, q0.y);
        fma2(acc[2][2], a2, q1.x); fma2(acc[2][3], a2, q1.y);
        fma2(acc[3][0], a3, q0.x); fma2(acc[3][1], a3, q0.y);
        fma2(acc[3][2], a3, q1.x); fma2(acc[3][3], a3, q1.y);
    }

    #pragma unroll
    for (int p = 0; p < 4; p++) {
        float b_lo = __ldg(b1 + c0 + 2 * p);
        float b_hi = __ldg(b1 + c0 + 2 * p + 1);
        #pragma unroll
        for (int i = 0; i < 4; i++) {
            float2 f = unpack2(acc[i][p]);
            H1[(r0 + i) * H1_STRIDE + c0 + 2 * p]     = fmaxf(f.x + b_lo, 0.f);
            H1[(r0 + i) * H1_STRIDE + c0 + 2 * p + 1] = fmaxf(f.y + b_hi, 0.f);
        }
    }
    __syncthreads();

    #pragma unroll
    for (int i = 0; i < 16; i++) Ws4[tid + i * 256] = W2[tid + i * 256];
    if (tid < DIM) { As[tid] = 0.f; As[DIM + tid] = 0.f; }
    __syncthreads();

    // ---- GEMM 2: acc = H1 @ W2 ----
    #pragma unroll
    for (int i = 0; i < 4; i++)
        #pragma unroll
        for (int p = 0; p < 4; p++) acc[i][p] = 0ull;

    #pragma unroll 4
    for (int k = 0; k < DIM; k++) {
        unsigned long long a0 = pack2(H1[(r0 + 0) * H1_STRIDE + k]);
        unsigned long long a1 = pack2(H1[(r0 + 1) * H1_STRIDE + k]);
        unsigned long long a2 = pack2(H1[(r0 + 2) * H1_STRIDE + k]);
        unsigned long long a3 = pack2(H1[(r0 + 3) * H1_STRIDE + k]);
        ulonglong2 q0 = Wp[k * 32 + colg * 2];
        ulonglong2 q1 = Wp[k * 32 + colg * 2 + 1];
        fma2(acc[0][0], a0, q0.x); fma2(acc[0][1], a0, q0.y);
        fma2(acc[0][2], a0, q1.x); fma2(acc[0][3], a0, q1.y);
        fma2(acc[1][0], a1, q0.x); fma2(acc[1][1], a1, q0.y);
        fma2(acc[1][2], a1, q1.x); fma2(acc[1][3], a1, q1.y);
        fma2(acc[2][0], a2, q0.x); fma2(acc[2][1], a2, q0.y);
        fma2(acc[2][2], a2, q1.x); fma2(acc[2][3], a2, q1.y);
        fma2(acc[3][0], a3, q0.x); fma2(acc[3][1], a3, q0.y);
        fma2(acc[3][2], a3, q1.x); fma2(acc[3][3], a3, q1.y);
    }

    float v[4][8];
    #pragma unroll
    for (int p = 0; p < 4; p++) {
        float b_lo = __ldg(b2 + c0 + 2 * p);
        float b_hi = __ldg(b2 + c0 + 2 * p + 1);
        #pragma unroll
        for (int i = 0; i < 4; i++) {
            float2 f = unpack2(acc[i][p]);
            v[i][2 * p]     = fmaxf(f.x + b_lo, 0.f);
            v[i][2 * p + 1] = fmaxf(f.y + b_hi, 0.f);
        }
    }

    float4* O4 = (float4*)g_agg;
    #pragma unroll
    for (int i = 0; i < 4; i++) {
        int row = base + r0 + i;
        if (row < N_NODES) {
            O4[row * 32 + colg * 2]     = make_float4(v[i][0], v[i][1], v[i][2], v[i][3]);
            O4[row * 32 + colg * 2 + 1] = make_float4(v[i][4], v[i][5], v[i][6], v[i][7]);
        }
    }

    #pragma unroll
    for (int j = 0; j < 8; j++) {
        float s = 0.f, q = 0.f;
        #pragma unroll
        for (int i = 0; i < 4; i++) {
            if (base + r0 + i < N_NODES) { s += v[i][j]; q += v[i][j] * v[i][j]; }
        }
        atomicAdd(&As[c0 + j], s);
        atomicAdd(&As[DIM + c0 + j], q);
    }
    __syncthreads();
    if (tid < DIM) {
        atomicAdd(&g_stats[tid], As[tid]);
        atomicAdd(&g_stats[DIM + tid], As[DIM + tid]);
    }
}

// ===========================================================================
// K3: apply BN -> g_h, pool into output (scale/shift computed per block)
// ===========================================================================
__global__ void k_apply(const int* __restrict__ batch, float* __restrict__ out,
                        const float* __restrict__ gamma, const float* __restrict__ beta,
                        int layer) {
    __shared__ float s_st[2 * DIM];
    if (threadIdx.x < DIM) {
        int f = threadIdx.x;
        float n = (float)N_NODES;
        float mean = g_stats[f] / n;
        float var = g_stats[DIM + f] / n - mean * mean;
        var = fmaxf(var, 0.f);
        float sc = rsqrtf(var + BN_EPS) * __ldg(gamma + f);
        s_st[f] = sc;
        s_st[DIM + f] = fmaf(-mean, sc, __ldg(beta + f));
    }
    __syncthreads();

    int idx = blockIdx.x * blockDim.x + threadIdx.x;  // 1.6M exact
    int row = idx >> 5, cq = idx & 31;
    float4 xv = ((const float4*)g_agg)[idx];
    float4 s = ((const float4*)s_st)[cq];
    float4 t = ((const float4*)s_st)[32 + cq];
    float4 y;
    y.x = fmaf(xv.x, s.x, t.x);
    y.y = fmaf(xv.y, s.y, t.y);
    y.z = fmaf(xv.z, s.z, t.z);
    y.w = fmaf(xv.w, s.w, t.w);
    ((float4*)g_h)[idx] = y;
    int g = __ldg(batch + row);
    red_add_v4((float4*)(out + g * (N_LAYERS * DIM) + layer * DIM + (cq << 2)), y);
}

// ---------------------------------------------------------------------------
extern "C" void kernel_launch(void* const* d_in, const int* in_sizes, int n_in,
                              void* d_out, int out_size) {
    const float* x      = (const float*)d_in[0];
    const int*   ei     = (const int*)d_in[1];
    const int*   batch  = (const int*)d_in[2];
    const float* W1s    = (const float*)d_in[3];
    const float* b1s    = (const float*)d_in[4];
    const float* W2s    = (const float*)d_in[5];
    const float* b2s    = (const float*)d_in[6];
    const float* gammas = (const float*)d_in[7];
    const float* betas  = (const float*)d_in[8];
    float* out = (float*)d_out;

    const int smem_mlp = (ROWS_PER_BLK * DIM + DIM * DIM + ROWS_PER_BLK * H1_STRIDE) * 4;
    cudaFuncSetAttribute(k_mlp, cudaFuncAttributeMaxDynamicSharedMemorySize, smem_mlp);

    cudaMemsetAsync(out, 0, (size_t)N_GRAPHS * N_LAYERS * DIM * sizeof(float));

    const int* src = ei;
    const int* dst = ei + N_EDGES;

    const int node_blocks = (N_NODES * 32) / 256;                          // 6250
    const int edge_blocks = (N_EDGES + 255) / 256;                         // 2344
    const int cnt_blocks  = (N_NODES + 255) / 256;                         // 196
    const int mlp_blocks  = (N_NODES + ROWS_PER_BLK - 1) / ROWS_PER_BLK;   // 782

    // --- build CSR once (edges shared by all layers) ---
    k_zero_counts<<<cnt_blocks, 256>>>();
    k_hist<<<edge_blocks, 256>>>(dst);
    k_scan1<<<SCAN_BLOCKS, 256>>>();
    k_scan2<<<1, 256>>>();
    k_scan3<<<SCAN_BLOCKS, 256>>>();
    k_place<<<edge_blocks, 256>>>(src, dst);

    for (int l = 0; l < N_LAYERS; l++) {
        int use_x = (l == 0) ? 1 : 0;
        k_agg<<<node_blocks, 256>>>((const float4*)x, use_x);
        k_mlp<<<mlp_blocks, 256, smem_mlp>>>(
            (const float4*)(W1s + l * DIM * DIM), b1s + l * DIM,
            (const float4*)(W2s + l * DIM * DIM), b2s + l * DIM);
        k_apply<<<node_blocks, 256>>>(batch, out, gammas + l * DIM, betas + l * DIM, l);
    }
}